// round 5
// baseline (speedup 1.0000x reference)
#include <cuda_runtime.h>
#include <math.h>

// Problem constants (fixed by the dataset)
#define E_NUM 32768
#define BATCH 128     // == H
#define DIM   1024    // IMG_DIM == TXT_DIM
#define GRID  148     // one block per SM -> all blocks co-resident (required!)
#define TPB   512

// ---- device scratch (allocation-free: __device__ globals) ----
__device__ __align__(16) float g_imgT [DIM * BATCH];   // img^T  [i][b]
__device__ __align__(16) float g_txtT [DIM * BATCH];   // text^T [t][b]
__device__ __align__(16) float g_W1aT [BATCH * BATCH]; // W1[:, :128]^T  [b][j]
__device__ __align__(16) float g_W1bT [BATCH * BATCH]; // W1[:, 128:]^T  [b][j]
__device__ __align__(16) float g_UT   [DIM * BATCH];   // (W1a @ img + b1)^T [s][j]
__device__ __align__(16) float g_VT   [DIM * BATCH];   // (W1b @ text)^T     [t][j]
__device__ __align__(16) float g_oImgT[DIM * BATCH];   // attended_img^T  [i][b]
__device__ __align__(16) float g_oTxtT[DIM * BATCH];   // attended_text^T [t][b]

// ---- software grid barrier (sense-reversal via monotonic epoch) ----
__device__ unsigned g_cnt   = 0;
__device__ unsigned g_epoch = 0;

__device__ __forceinline__ void grid_bar() {
    __syncthreads();
    if (threadIdx.x == 0) {
        __threadfence();   // make this block's writes visible (also flushes L1)
        unsigned e = *(volatile unsigned*)&g_epoch;
        if (atomicAdd(&g_cnt, 1u) == GRID - 1) {
            g_cnt = 0;
            __threadfence();
            atomicAdd(&g_epoch, 1u);            // release
        } else {
            while (*(volatile unsigned*)&g_epoch == e) { }
        }
        __threadfence();   // acquire: invalidate stale L1 before consuming
    }
    __syncthreads();
}

__global__ void __launch_bounds__(TPB, 1)
mono_kernel(const float* __restrict__ img, const float* __restrict__ txt,
            const int* __restrict__ src, const int* __restrict__ tgt,
            const float* __restrict__ W1, const float* __restrict__ b1,
            const float* __restrict__ w2, const float* __restrict__ b2,
            float* __restrict__ out) {
    __shared__ __align__(16) float sh[2176];
    const int tid = threadIdx.x;
    const int bid = blockIdx.x;

    // ================= P0: transposes + accumulator zeroing =================
    {
        int gid = bid * TPB + tid;
        if (gid < (DIM * BATCH) / 4) {
            float4 z = make_float4(0.f, 0.f, 0.f, 0.f);
            ((float4*)g_oImgT)[gid] = z;
            ((float4*)g_oTxtT)[gid] = z;
        }
        // 144 transpose strips: 16 input-cols x 128 input-rows each
        if (bid < 144) {
            const float* in; float* o; int stride, col0;
            if (bid < 64)       { in = img;        stride = DIM;       o = g_imgT; col0 = bid * 16; }
            else if (bid < 128) { in = txt;        stride = DIM;       o = g_txtT; col0 = (bid - 64) * 16; }
            else if (bid < 136) { in = W1;         stride = 2 * BATCH; o = g_W1aT; col0 = (bid - 128) * 16; }
            else                { in = W1 + BATCH; stride = 2 * BATCH; o = g_W1bT; col0 = (bid - 136) * 16; }

            int x = tid & 15, y = tid >> 4;           // y in [0,32)
#pragma unroll
            for (int k = 0; k < 4; ++k) {
                int r = y + 32 * k;                   // input row
                sh[r * 17 + x] = in[r * stride + col0 + x];
            }
            __syncthreads();
            int cl = tid & 15, v = tid >> 4;          // v in [0,32)
            float4 val;
            val.x = sh[(4 * v + 0) * 17 + cl];
            val.y = sh[(4 * v + 1) * 17 + cl];
            val.z = sh[(4 * v + 2) * 17 + cl];
            val.w = sh[(4 * v + 3) * 17 + cl];
            ((float4*)(o + (col0 + cl) * BATCH))[v] = val;
        }
    }
    grid_bar();

    // ================= P1: U/V GEMMs (per-column, W stays L1-hot) ===========
    {
        int j = tid & 127, cl = tid >> 7;             // 4 columns per block-task
        for (int t = bid; t < 512; t += GRID) {
            bool isV = t >= 256;
            int  c0  = (t & 255) * 4;
            const float* feat = isV ? g_txtT : g_imgT;
            const float* Wt   = isV ? g_W1bT : g_W1aT;

            __syncthreads();                          // protect sh reuse
            sh[tid] = feat[c0 * BATCH + tid];         // 4 contiguous feature rows
            __syncthreads();

            float acc = isV ? 0.0f : b1[j];
            const float* xrow = sh + cl * BATCH;
#pragma unroll 8
            for (int b = 0; b < BATCH; ++b)
                acc = fmaf(Wt[b * BATCH + j], xrow[b], acc);

            (isV ? g_VT : g_UT)[(c0 + cl) * BATCH + j] = acc;
        }
    }
    grid_bar();

    // ================= P2: per-edge MLP + v4-RED scatter =====================
    {
        int lane = tid & 31;
        int wgid = bid * 16 + (tid >> 5);
        float4 w = reinterpret_cast<const float4*>(w2)[lane];
        float bias2 = b2[0];

        for (int e = wgid; e < E_NUM; e += GRID * 16) {
            int s = src[e];
            int t = tgt[e];

            float4 u = reinterpret_cast<const float4*>(g_UT + s * BATCH)[lane];
            float4 v = reinterpret_cast<const float4*>(g_VT + t * BATCH)[lane];

            float h0 = fmaxf(u.x + v.x, 0.0f);
            float h1 = fmaxf(u.y + v.y, 0.0f);
            float h2 = fmaxf(u.z + v.z, 0.0f);
            float h3 = fmaxf(u.w + v.w, 0.0f);

            float p = fmaf(h0, w.x, fmaf(h1, w.y, fmaf(h2, w.z, h3 * w.w)));
#pragma unroll
            for (int off = 16; off; off >>= 1)
                p += __shfl_xor_sync(0xffffffffu, p, off);

            float a = 1.0f / (1.0f + __expf(-(p + bias2)));

            float4 tx = reinterpret_cast<const float4*>(g_txtT + t * BATCH)[lane];
            float4 im = reinterpret_cast<const float4*>(g_imgT + s * BATCH)[lane];

            float* oi = g_oImgT + s * BATCH + lane * 4;
            float* ot = g_oTxtT + t * BATCH + lane * 4;

            asm volatile("red.global.v4.f32.add [%0], {%1, %2, %3, %4};"
                         :: "l"(oi), "f"(a * tx.x), "f"(a * tx.y), "f"(a * tx.z), "f"(a * tx.w)
                         : "memory");
            asm volatile("red.global.v4.f32.add [%0], {%1, %2, %3, %4};"
                         :: "l"(ot), "f"(a * im.x), "f"(a * im.y), "f"(a * im.z), "f"(a * im.w)
                         : "memory");
        }
    }
    grid_bar();

    // ================= P3: transpose accumulators into output layout ========
    // 128 strips: 16 dim-rows x 128 batch each. out[b][d] = oT[d][b].
    if (bid < 128) {
        int side = bid >> 6;
        int d0   = (bid & 63) * 16;
        const float* in = side ? g_oTxtT : g_oImgT;
        float* o = out + (size_t)side * BATCH * DIM;

        int d = tid >> 5, v = tid & 31;
        float4 t4 = reinterpret_cast<const float4*>(in + (d0 + d) * BATCH)[v];
        ((float4*)(sh + d * 132))[v] = t4;            // sh[16][132]
        __syncthreads();

        int b  = tid & 127;
        int k4 = (tid >> 7) * 4;
        float4 val;
        val.x = sh[(k4 + 0) * 132 + b];
        val.y = sh[(k4 + 1) * 132 + b];
        val.z = sh[(k4 + 2) * 132 + b];
        val.w = sh[(k4 + 3) * 132 + b];
        ((float4*)(o + b * DIM + d0))[k4 >> 2] = val;
    }
}

extern "C" void kernel_launch(void* const* d_in, const int* in_sizes, int n_in,
                              void* d_out, int out_size) {
    const float* img = (const float*)d_in[0];   // [128, 1024]
    const float* txt = (const float*)d_in[1];   // [128, 1024]
    const int*   src = (const int*)  d_in[2];   // [32768]
    const int*   tgt = (const int*)  d_in[3];   // [32768]
    const float* W1  = (const float*)d_in[4];   // [128, 256]
    const float* b1  = (const float*)d_in[5];   // [128]
    const float* w2  = (const float*)d_in[6];   // [128]
    const float* b2  = (const float*)d_in[7];   // [1]
    float* out = (float*)d_out;                 // [2 * 128 * 1024]

    mono_kernel<<<GRID, TPB>>>(img, txt, src, tgt, W1, b1, w2, b2, out);
}

// round 6
// speedup vs baseline: 1.7047x; 1.7047x over previous
#include <cuda_runtime.h>
#include <math.h>

// Problem constants (fixed by the dataset)
#define E_NUM 32768
#define BATCH 128     // == H
#define DIM   1024    // IMG_DIM == TXT_DIM

// ---- device scratch (allocation-free: __device__ globals) ----
__device__ float g_imgT [DIM * BATCH];   // img^T  [i][b]
__device__ float g_txtT [DIM * BATCH];   // text^T [t][b]
__device__ float g_W1aT [BATCH * BATCH]; // W1[:, :128]^T  -> [b][j]
__device__ float g_W1bT [BATCH * BATCH]; // W1[:, 128:]^T  -> [b][j]
__device__ float g_UT   [DIM * BATCH];   // (W1a @ img + b1)^T : [s][j]
__device__ float g_VT   [DIM * BATCH];   // (W1b @ text)^T     : [t][j]
__device__ float g_oImgT[DIM * BATCH];   // attended_img^T [i][b]
__device__ float g_oTxtT[DIM * BATCH];   // attended_text^T [t][b]

// ---- fused transposes: one launch (first kernel: plain launch, full barrier
// against the previous graph replay) ----
__global__ void k_prep(const float* __restrict__ img, const float* __restrict__ txt,
                       const float* __restrict__ W1) {
    __shared__ float tile[32][33];
    int id = blockIdx.x;

    const float* in;
    float* out;
    int in_stride, bx, by;
    if (id < 256) {
        bool isTxt = id >= 128;
        int lid = id & 127;
        in = (isTxt ? txt : img);
        out = isTxt ? g_txtT : g_imgT;
        in_stride = DIM;
        bx = lid & 31;
        by = lid >> 5;
    } else {
        bool isB = id >= 272;
        int lid = (id - 256) & 15;
        in = W1 + (isB ? BATCH : 0);
        out = isB ? g_W1bT : g_W1aT;
        in_stride = 2 * BATCH;
        bx = lid & 3;
        by = lid >> 2;
    }

    int x = bx * 32 + threadIdx.x;
    int y = by * 32 + threadIdx.y;
    tile[threadIdx.y][threadIdx.x] = in[(long)y * in_stride + x];
    __syncthreads();
    int ox = by * 32 + threadIdx.x;
    int oy = bx * 32 + threadIdx.y;
    out[(long)oy * BATCH + ox] = tile[threadIdx.x][threadIdx.y];
}

// ---- UT[s][j] = b1[j] + sum_b W1aT[b][j]*imgT[s][b]
//      VT[t][j] =         sum_b W1bT[b][j]*txtT[t][b]
// PDL: zero accumulators (independent of k_prep) BEFORE the dependency sync.
__global__ void k_uv(const float* __restrict__ b1) {
    int  col = blockIdx.x & (DIM - 1);
    bool isV = blockIdx.x >= DIM;
    int  j   = threadIdx.x;

    // fused accumulator zeroing for the scatter phase (no upstream dependency)
    int zidx = col * BATCH + j;
    (isV ? g_oTxtT : g_oImgT)[zidx] = 0.0f;

    float bias = isV ? 0.0f : b1[j];   // kernel input, not produced upstream

    // now wait for k_prep's transposes
    cudaGridDependencySynchronize();

    const float* x  = (isV ? g_txtT : g_imgT) + col * BATCH;
    const float* Wt =  isV ? g_W1bT : g_W1aT;

    __shared__ float xs[BATCH];
    xs[j] = x[j];
    __syncthreads();

    float acc = bias;
#pragma unroll 16
    for (int b = 0; b < BATCH; ++b)
        acc = fmaf(Wt[b * BATCH + j], xs[b], acc);

    (isV ? g_VT : g_UT)[col * BATCH + j] = acc;
}

// ---- per-edge: a = sigmoid(w2 . relu(UT[s] + VT[t]) + b2), then scatter:
//      oImgT[s][:] += a * txtT[t][:];  oTxtT[t][:] += a * imgT[s][:]
// PDL: load edge indices + weights (kernel inputs) before the sync.
__global__ void k_edge(const int* __restrict__ src, const int* __restrict__ tgt,
                       const float* __restrict__ w2, const float* __restrict__ b2) {
    int warp = threadIdx.x >> 5;
    int lane = threadIdx.x & 31;
    int e    = blockIdx.x * 8 + warp;

    int s = src[e];
    int t = tgt[e];
    float4 w = reinterpret_cast<const float4*>(w2)[lane];
    float bias2 = b2[0];

    // wait for k_uv (UT/VT) — accumulators were zeroed by k_uv too
    cudaGridDependencySynchronize();

    float4 u = reinterpret_cast<const float4*>(g_UT + s * BATCH)[lane];
    float4 v = reinterpret_cast<const float4*>(g_VT + t * BATCH)[lane];

    float h0 = fmaxf(u.x + v.x, 0.0f);
    float h1 = fmaxf(u.y + v.y, 0.0f);
    float h2 = fmaxf(u.z + v.z, 0.0f);
    float h3 = fmaxf(u.w + v.w, 0.0f);

    float p = fmaf(h0, w.x, fmaf(h1, w.y, fmaf(h2, w.z, h3 * w.w)));
#pragma unroll
    for (int off = 16; off; off >>= 1)
        p += __shfl_xor_sync(0xffffffffu, p, off);

    float a = 1.0f / (1.0f + __expf(-(p + bias2)));

    float4 tx = reinterpret_cast<const float4*>(g_txtT + t * BATCH)[lane];
    float4 im = reinterpret_cast<const float4*>(g_imgT + s * BATCH)[lane];

    float* oi = g_oImgT + s * BATCH + lane * 4;
    float* ot = g_oTxtT + t * BATCH + lane * 4;

    asm volatile("red.global.v4.f32.add [%0], {%1, %2, %3, %4};"
                 :: "l"(oi), "f"(a * tx.x), "f"(a * tx.y), "f"(a * tx.z), "f"(a * tx.w)
                 : "memory");
    asm volatile("red.global.v4.f32.add [%0], {%1, %2, %3, %4};"
                 :: "l"(ot), "f"(a * im.x), "f"(a * im.y), "f"(a * im.z), "f"(a * im.w)
                 : "memory");
}

// ---- final transpose of accumulators into the output layout ----
__global__ void k_writeout(float* __restrict__ out) {
    // out[0 .. 128*1024)          = attended_img  [b][i] = oImgT[i][b]
    // out[128*1024 .. 2*128*1024) = attended_text [b][t] = oTxtT[t][b]
    cudaGridDependencySynchronize();   // wait for k_edge's scatters

    __shared__ float tile[32][33];
    bool second = blockIdx.z != 0;
    const float* in = second ? g_oTxtT : g_oImgT;
    float* o = out + (second ? (size_t)BATCH * DIM : 0);

    int x = blockIdx.x * 32 + threadIdx.x;   // b  (input col, 0..127)
    int y = blockIdx.y * 32 + threadIdx.y;   // i/t (input row, 0..1023)
    tile[threadIdx.y][threadIdx.x] = in[(long)y * BATCH + x];
    __syncthreads();
    int ox = blockIdx.y * 32 + threadIdx.x;  // i/t
    int oy = blockIdx.x * 32 + threadIdx.y;  // b
    o[(long)oy * DIM + ox] = tile[threadIdx.x][threadIdx.y];
}

extern "C" void kernel_launch(void* const* d_in, const int* in_sizes, int n_in,
                              void* d_out, int out_size) {
    const float* img = (const float*)d_in[0];   // [128, 1024]
    const float* txt = (const float*)d_in[1];   // [128, 1024]
    const int*   src = (const int*)  d_in[2];   // [32768]
    const int*   tgt = (const int*)  d_in[3];   // [32768]
    const float* W1  = (const float*)d_in[4];   // [128, 256]
    const float* b1  = (const float*)d_in[5];   // [128]
    const float* w2  = (const float*)d_in[6];   // [128]
    const float* b2  = (const float*)d_in[7];   // [1]
    float* out = (float*)d_out;                 // [2 * 128 * 1024]

    // 1) fused transposes — plain launch (serializes against prior replay)
    k_prep<<<288, dim3(32, 32)>>>(img, txt, W1);

    // PDL attribute: downstream kernels may launch while predecessor runs;
    // device-side cudaGridDependencySynchronize() enforces the data dependency.
    cudaLaunchAttribute attr;
    attr.id = cudaLaunchAttributeProgrammaticStreamSerialization;
    attr.val.programmaticStreamSerializationAllowed = 1;

    // 2) U/V GEMMs + accumulator zeroing
    {
        cudaLaunchConfig_t cfg = {};
        cfg.gridDim  = dim3(2 * DIM);
        cfg.blockDim = dim3(BATCH);
        cfg.attrs = &attr;
        cfg.numAttrs = 1;
        cudaLaunchKernelEx(&cfg, k_uv, b1);
    }

    // 3) per-edge MLP + vectorized scatter-accumulate
    {
        cudaLaunchConfig_t cfg = {};
        cfg.gridDim  = dim3(E_NUM / 8);
        cfg.blockDim = dim3(256);
        cfg.attrs = &attr;
        cfg.numAttrs = 1;
        cudaLaunchKernelEx(&cfg, k_edge, src, tgt, w2, b2);
    }

    // 4) transpose accumulators into the output layout
    {
        cudaLaunchConfig_t cfg = {};
        cfg.gridDim  = dim3(BATCH / 32, DIM / 32, 2);
        cfg.blockDim = dim3(32, 32);
        cfg.attrs = &attr;
        cfg.numAttrs = 1;
        cudaLaunchKernelEx(&cfg, k_writeout, out);
    }
}

// round 7
// speedup vs baseline: 1.7260x; 1.0125x over previous
#include <cuda_runtime.h>
#include <math.h>

// Problem constants (fixed by the dataset)
#define E_NUM 32768
#define BATCH 128     // == H
#define DIM   1024    // IMG_DIM == TXT_DIM

// ---- device scratch (allocation-free: __device__ globals) ----
__device__ float g_imgT [DIM * BATCH];   // img^T  [i][b]
__device__ float g_txtT [DIM * BATCH];   // text^T [t][b]
__device__ float g_W1aT [BATCH * BATCH]; // W1[:, :128]^T  -> [b][j]
__device__ float g_W1bT [BATCH * BATCH]; // W1[:, 128:]^T  -> [b][j]
__device__ float g_UT   [DIM * BATCH];   // (W1a @ img + b1)^T : [s][j]
__device__ float g_VT   [DIM * BATCH];   // (W1b @ text)^T     : [t][j]
__device__ float g_oImgT[DIM * BATCH];   // attended_img^T [i][b]
__device__ float g_oTxtT[DIM * BATCH];   // attended_text^T [t][b]

// ---- fused transposes. PDL: overlaps the PREVIOUS replay's k_writeout.
// Safe: writes here are disjoint from writeout's reads, and all values written
// are byte-identical across replays (deterministic from constant inputs).
__global__ void k_prep(const float* __restrict__ img, const float* __restrict__ txt,
                       const float* __restrict__ W1) {
    __shared__ float tile[32][33];
    int id = blockIdx.x;

    const float* in;
    float* out;
    int in_stride, bx, by;
    if (id < 256) {
        bool isTxt = id >= 128;
        int lid = id & 127;
        in = (isTxt ? txt : img);
        out = isTxt ? g_txtT : g_imgT;
        in_stride = DIM;
        bx = lid & 31;
        by = lid >> 5;
    } else {
        bool isB = id >= 272;
        int lid = (id - 256) & 15;
        in = W1 + (isB ? BATCH : 0);
        out = isB ? g_W1bT : g_W1aT;
        in_stride = 2 * BATCH;
        bx = lid & 3;
        by = lid >> 2;
    }

    int x = bx * 32 + threadIdx.x;
    int y = by * 32 + threadIdx.y;
    tile[threadIdx.y][threadIdx.x] = in[(long)y * in_stride + x];
    __syncthreads();
    int ox = by * 32 + threadIdx.x;
    int oy = bx * 32 + threadIdx.y;
    out[(long)oy * BATCH + ox] = tile[threadIdx.x][threadIdx.y];
}

// ---- UT[s][j] = b1[j] + sum_b W1aT[b][j]*imgT[s][b]
//      VT[t][j] =         sum_b W1bT[b][j]*txtT[t][b]
// PDL: zero accumulators (independent of k_prep) BEFORE the dependency sync.
__global__ void k_uv(const float* __restrict__ b1) {
    int  col = blockIdx.x & (DIM - 1);
    bool isV = blockIdx.x >= DIM;
    int  j   = threadIdx.x;

    // fused accumulator zeroing for the scatter phase (no upstream dependency)
    int zidx = col * BATCH + j;
    (isV ? g_oTxtT : g_oImgT)[zidx] = 0.0f;

    float bias = isV ? 0.0f : b1[j];   // kernel input, not produced upstream

    // now wait for k_prep's transposes
    cudaGridDependencySynchronize();

    const float* x  = (isV ? g_txtT : g_imgT) + col * BATCH;
    const float* Wt =  isV ? g_W1bT : g_W1aT;

    __shared__ float xs[BATCH];
    xs[j] = x[j];
    __syncthreads();

    float acc = bias;
#pragma unroll 16
    for (int b = 0; b < BATCH; ++b)
        acc = fmaf(Wt[b * BATCH + j], xs[b], acc);

    (isV ? g_VT : g_UT)[col * BATCH + j] = acc;
}

// ---- per-edge: a = sigmoid(w2 . relu(UT[s] + VT[t]) + b2), then scatter:
//      oImgT[s][:] += a * txtT[t][:];  oTxtT[t][:] += a * imgT[s][:]
// PDL: load edge indices + weights (kernel inputs) before the sync.
__global__ void k_edge(const int* __restrict__ src, const int* __restrict__ tgt,
                       const float* __restrict__ w2, const float* __restrict__ b2) {
    int warp = threadIdx.x >> 5;
    int lane = threadIdx.x & 31;
    int e    = blockIdx.x * 8 + warp;

    int s = src[e];
    int t = tgt[e];
    float4 w = reinterpret_cast<const float4*>(w2)[lane];
    float bias2 = b2[0];

    // wait for k_uv (UT/VT) — accumulators were zeroed by k_uv too
    cudaGridDependencySynchronize();

    float4 u = reinterpret_cast<const float4*>(g_UT + s * BATCH)[lane];
    float4 v = reinterpret_cast<const float4*>(g_VT + t * BATCH)[lane];

    float h0 = fmaxf(u.x + v.x, 0.0f);
    float h1 = fmaxf(u.y + v.y, 0.0f);
    float h2 = fmaxf(u.z + v.z, 0.0f);
    float h3 = fmaxf(u.w + v.w, 0.0f);

    float p = fmaf(h0, w.x, fmaf(h1, w.y, fmaf(h2, w.z, h3 * w.w)));
#pragma unroll
    for (int off = 16; off; off >>= 1)
        p += __shfl_xor_sync(0xffffffffu, p, off);

    float a = __fdividef(1.0f, 1.0f + __expf(-(p + bias2)));

    float4 tx = reinterpret_cast<const float4*>(g_txtT + t * BATCH)[lane];
    float4 im = reinterpret_cast<const float4*>(g_imgT + s * BATCH)[lane];

    float* oi = g_oImgT + s * BATCH + lane * 4;
    float* ot = g_oTxtT + t * BATCH + lane * 4;

    asm volatile("red.global.v4.f32.add [%0], {%1, %2, %3, %4};"
                 :: "l"(oi), "f"(a * tx.x), "f"(a * tx.y), "f"(a * tx.z), "f"(a * tx.w)
                 : "memory");
    asm volatile("red.global.v4.f32.add [%0], {%1, %2, %3, %4};"
                 :: "l"(ot), "f"(a * im.x), "f"(a * im.y), "f"(a * im.z), "f"(a * im.w)
                 : "memory");
}

// ---- final transpose of accumulators into the output layout ----
__global__ void k_writeout(float* __restrict__ out) {
    // out[0 .. 128*1024)          = attended_img  [b][i] = oImgT[i][b]
    // out[128*1024 .. 2*128*1024) = attended_text [b][t] = oTxtT[t][b]
    cudaGridDependencySynchronize();   // wait for k_edge's scatters

    __shared__ float tile[32][33];
    bool second = blockIdx.z != 0;
    const float* in = second ? g_oTxtT : g_oImgT;
    float* o = out + (second ? (size_t)BATCH * DIM : 0);

    int x = blockIdx.x * 32 + threadIdx.x;   // b  (input col, 0..127)
    int y = blockIdx.y * 32 + threadIdx.y;   // i/t (input row, 0..1023)
    tile[threadIdx.y][threadIdx.x] = in[(long)y * BATCH + x];
    __syncthreads();
    int ox = blockIdx.y * 32 + threadIdx.x;  // i/t
    int oy = blockIdx.x * 32 + threadIdx.y;  // b
    o[(long)oy * DIM + ox] = tile[threadIdx.x][threadIdx.y];
}

extern "C" void kernel_launch(void* const* d_in, const int* in_sizes, int n_in,
                              void* d_out, int out_size) {
    const float* img = (const float*)d_in[0];   // [128, 1024]
    const float* txt = (const float*)d_in[1];   // [128, 1024]
    const int*   src = (const int*)  d_in[2];   // [32768]
    const int*   tgt = (const int*)  d_in[3];   // [32768]
    const float* W1  = (const float*)d_in[4];   // [128, 256]
    const float* b1  = (const float*)d_in[5];   // [128]
    const float* w2  = (const float*)d_in[6];   // [128]
    const float* b2  = (const float*)d_in[7];   // [1]
    float* out = (float*)d_out;                 // [2 * 128 * 1024]

    cudaLaunchAttribute attr;
    attr.id = cudaLaunchAttributeProgrammaticStreamSerialization;
    attr.val.programmaticStreamSerializationAllowed = 1;

    // 1) fused transposes — PDL: overlaps previous replay's writeout
    {
        cudaLaunchConfig_t cfg = {};
        cfg.gridDim  = dim3(288);
        cfg.blockDim = dim3(32, 32);
        cfg.attrs = &attr;
        cfg.numAttrs = 1;
        cudaLaunchKernelEx(&cfg, k_prep, img, txt, W1);
    }

    // 2) U/V GEMMs + accumulator zeroing
    {
        cudaLaunchConfig_t cfg = {};
        cfg.gridDim  = dim3(2 * DIM);
        cfg.blockDim = dim3(BATCH);
        cfg.attrs = &attr;
        cfg.numAttrs = 1;
        cudaLaunchKernelEx(&cfg, k_uv, b1);
    }

    // 3) per-edge MLP + vectorized scatter-accumulate
    {
        cudaLaunchConfig_t cfg = {};
        cfg.gridDim  = dim3(E_NUM / 8);
        cfg.blockDim = dim3(256);
        cfg.attrs = &attr;
        cfg.numAttrs = 1;
        cudaLaunchKernelEx(&cfg, k_edge, src, tgt, w2, b2);
    }

    // 4) transpose accumulators into the output layout
    {
        cudaLaunchConfig_t cfg = {};
        cfg.gridDim  = dim3(BATCH / 32, DIM / 32, 2);
        cfg.blockDim = dim3(32, 32);
        cfg.attrs = &attr;
        cfg.numAttrs = 1;
        cudaLaunchKernelEx(&cfg, k_writeout, out);
    }
}